// round 15
// baseline (speedup 1.0000x reference)
#include <cuda_runtime.h>
#include <cuda_fp16.h>
#include <math.h>

#define N_NODES 100000
#define N_EDGES 1600000
#define NH 4
#define DIN 128
#define DOUT 32
#define NB_SCAN 98   // 98*1024 = 100352 >= N_NODES

#define CTOT 128              // NH*DOUT combined output cols
#define WPITCH 132            // smem pitch for W (conflict-free LDS.128)
#define NPB 64                // gemm nodes per block (256 threads, 2 CTA/SM)
#define GEMM_SMEM ((CTOT*WPITCH + NPB*DIN) * 4)   // 67584 + 32768 = 100352 B

// ---------------- scratch (static __device__, no allocation) ----------------
__device__ __align__(16) __half d_Hwh[N_NODES * CTOT];  // [n][c] fp16, 25.6MB
__device__ float4 d_ssrc4[N_NODES];       // [n] -> (s_src for h=0..3)
__device__ float4 d_stgt4[N_NODES];
__device__ int    d_hist[N_NODES];
__device__ int    d_off[N_NODES + 1];
__device__ int    d_cursor[N_NODES];
__device__ int    d_blocksums[128];
__device__ int    d_sorted_src[N_EDGES];
__device__ int    d_is64;

__device__ __forceinline__ void fma2(unsigned long long& acc,
                                     unsigned long long a,
                                     unsigned long long b) {
    asm("fma.rn.f32x2 %0, %1, %2, %0;" : "+l"(acc) : "l"(a), "l"(b));
}
__device__ __forceinline__ float pairsum(unsigned long long a) {
    float lo = __uint_as_float((unsigned)(a & 0xffffffffull));
    float hi = __uint_as_float((unsigned)(a >> 32));
    return lo + hi;
}

// ---------------- init: zero hist + detect edge dtype ----------------
// int64 with values < 2^31 => every odd 32-bit word is zero.
__global__ void k_init(const unsigned int* __restrict__ w) {
    int i = blockIdx.x * 256 + threadIdx.x;
    if (i < N_NODES) d_hist[i] = 0;
    if (blockIdx.x == 0) {
        int nz = 0;
        for (int j = 0; j < 8; j++)
            nz |= (w[2 * (threadIdx.x * 8 + j) + 1] != 0u) ? 1 : 0;
        int any = __syncthreads_or(nz);
        if (threadIdx.x == 0) d_is64 = any ? 0 : 1;
    }
}

// histogram of targets, reading edge_index directly
__global__ void k_hist(const int* __restrict__ p) {
    int e = blockIdx.x * blockDim.x + threadIdx.x;
    if (e >= N_EDGES) return;
    int t = d_is64 ? p[2 * (N_EDGES + e)] : p[N_EDGES + e];
    atomicAdd(&d_hist[t], 1);
}

// ---------------- block sums of hist (shfl) ----------------
__global__ void k_scan1() {
    __shared__ int ws[8];
    int b = blockIdx.x, tid = threadIdx.x;
    int lane = tid & 31, wid = tid >> 5;
    int sum = 0;
    for (int j = 0; j < 4; j++) {
        int idx = b * 1024 + tid + j * 256;
        if (idx < N_NODES) sum += d_hist[idx];
    }
#pragma unroll
    for (int off = 16; off > 0; off >>= 1)
        sum += __shfl_xor_sync(0xffffffffu, sum, off);
    if (lane == 0) ws[wid] = sum;
    __syncthreads();
    if (tid == 0) {
        int s = 0;
        for (int j = 0; j < 8; j++) s += ws[j];
        d_blocksums[b] = s;
    }
}

// scan of hist: shfl-based, with inlined redundant scan of the 98 block sums
__global__ void k_scan3() {
    __shared__ int bs[128];
    __shared__ int warpsums[32];
    int b = blockIdx.x, tid = threadIdx.x;
    int lane = tid & 31, wid = tid >> 5;

    if (tid < 128) bs[tid] = (tid < NB_SCAN) ? d_blocksums[tid] : 0;
    __syncthreads();
    if (wid == 0) {
        int a0 = bs[4 * lane], a1 = bs[4 * lane + 1];
        int a2 = bs[4 * lane + 2], a3 = bs[4 * lane + 3];
        int s = a0 + a1 + a2 + a3;
        int inc = s;
#pragma unroll
        for (int off = 1; off < 32; off <<= 1) {
            int n = __shfl_up_sync(0xffffffffu, inc, off);
            if (lane >= off) inc += n;
        }
        int excl = inc - s;
        bs[4 * lane]     = excl;
        bs[4 * lane + 1] = excl + a0;
        bs[4 * lane + 2] = excl + a0 + a1;
        bs[4 * lane + 3] = excl + a0 + a1 + a2;
    }
    __syncthreads();
    int blockbase = bs[b];

    int idx = b * 1024 + tid;
    int v = (idx < N_NODES) ? d_hist[idx] : 0;
    int inc = v;
#pragma unroll
    for (int off = 1; off < 32; off <<= 1) {
        int n = __shfl_up_sync(0xffffffffu, inc, off);
        if (lane >= off) inc += n;
    }
    if (lane == 31) warpsums[wid] = inc;
    __syncthreads();
    if (wid == 0) {
        int wv = warpsums[lane];
        int winc = wv;
#pragma unroll
        for (int off = 1; off < 32; off <<= 1) {
            int n = __shfl_up_sync(0xffffffffu, winc, off);
            if (lane >= off) winc += n;
        }
        warpsums[lane] = winc - wv;
    }
    __syncthreads();
    if (idx < N_NODES) {
        int excl = inc - v + warpsums[wid] + blockbase;
        d_off[idx] = excl;
        d_cursor[idx] = excl;
    }
    if (b == 0 && tid == 0) d_off[N_NODES] = N_EDGES;
}

// scatter src ids into CSR order, reading edge_index directly
__global__ void k_scatter(const int* __restrict__ p) {
    int e = blockIdx.x * blockDim.x + threadIdx.x;
    if (e >= N_EDGES) return;
    int s, t;
    if (d_is64) {
        s = p[2 * e];
        t = p[2 * (N_EDGES + e)];
    } else {
        s = p[e];
        t = p[N_EDGES + e];
    }
    int pos = atomicAdd(&d_cursor[t], 1);
    d_sorted_src[pos] = s;
}

// ---------------- Hw[n][c] = sum_k Hin[n][k] * W[c][k]  (c = h*32+o) ----------
// 256 threads, tile 64 nodes x 128 cols, reg tile 8 nodes x 4 cols per thread,
// f32x2 packed FFMA, 2 CTAs/SM. Epilogue: fp16 Hw store + fused fp32 score
// reduction (warp owns all 128 cols of its 8 nodes; col group j == head j).
__global__ void __launch_bounds__(256, 2) k_gemm(const float* __restrict__ Hin,
                                                 const float* __restrict__ W,
                                                 const float* __restrict__ Asrc,
                                                 const float* __restrict__ Atgt) {
    extern __shared__ float smem[];
    float* Wsh = smem;                  // [128][WPITCH]
    float* Hsh = smem + CTOT * WPITCH;  // [64][128]

    int tid = threadIdx.x;
    int tx = tid & 31;   // col lane: cols tx + 32*j  (head j, out chan tx)
    int wp = tid >> 5;   // warp: nodes wp*8 + i

    const float4* W4 = (const float4*)W;
    for (int it = 0; it < 16; it++) {
        int idx = tid + it * 256;
        int c = idx >> 5, k4 = idx & 31;
        *(float4*)(Wsh + c * WPITCH + k4 * 4) = W4[idx];
    }

    int n0 = blockIdx.x * NPB;
    const float4* H4 = (const float4*)Hin;
    for (int it = 0; it < 8; it++) {
        int idx = tid + it * 256;
        int row = idx >> 5, c4 = idx & 31;
        int n = n0 + row;
        float4 v = make_float4(0.f, 0.f, 0.f, 0.f);
        if (n < N_NODES) v = H4[n * 32 + c4];
        *(float4*)(Hsh + row * DIN + c4 * 4) = v;
    }
    __syncthreads();

    unsigned long long acc[8][4];
#pragma unroll
    for (int i = 0; i < 8; i++)
#pragma unroll
        for (int j = 0; j < 4; j++) acc[i][j] = 0ull;

    const float* hbase = Hsh + (wp * 8) * DIN;
    const float* wbase = Wsh + tx * WPITCH;

#pragma unroll 2
    for (int k4 = 0; k4 < 32; k4++) {
        ulonglong2 wv[4];
#pragma unroll
        for (int j = 0; j < 4; j++)
            wv[j] = *(const ulonglong2*)(wbase + j * 32 * WPITCH + k4 * 4);
#pragma unroll
        for (int i = 0; i < 8; i++) {
            ulonglong2 hv = *(const ulonglong2*)(hbase + i * DIN + k4 * 4);
#pragma unroll
            for (int j = 0; j < 4; j++) {
                fma2(acc[i][j], hv.x, wv[j].x);
                fma2(acc[i][j], hv.y, wv[j].y);
            }
        }
    }

    float a_s[4], a_t[4];
#pragma unroll
    for (int j = 0; j < 4; j++) {
        a_s[j] = Asrc[j * 32 + tx];
        a_t[j] = Atgt[j * 32 + tx];
    }

#pragma unroll
    for (int i = 0; i < 8; i++) {
        int n = n0 + wp * 8 + i;
        if (n >= N_NODES) break;     // uniform across the warp
        float av[4], vs[4], vt[4];
#pragma unroll
        for (int j = 0; j < 4; j++) {
            av[j] = pairsum(acc[i][j]);
            vs[j] = av[j] * a_s[j];
            vt[j] = av[j] * a_t[j];
        }
#pragma unroll
        for (int j = 0; j < 4; j++)
            d_Hwh[n * CTOT + tx + 32 * j] = __float2half_rn(av[j]);
#pragma unroll
        for (int off = 16; off > 0; off >>= 1) {
#pragma unroll
            for (int j = 0; j < 4; j++) {
                vs[j] += __shfl_xor_sync(0xffffffffu, vs[j], off);
                vt[j] += __shfl_xor_sync(0xffffffffu, vt[j], off);
            }
        }
        if (tx == 0) {
            d_ssrc4[n] = make_float4(vs[0], vs[1], vs[2], vs[3]);
            d_stgt4[n] = make_float4(vt[0], vt[1], vt[2], vt[3]);
        }
    }
}

// ---------------- per-target softmax + aggregation + elu (all 4 heads) -------
// One warp per target node, single pass: unnormalized exp-weighted sums plus
// per-head denominators, normalize at the end. Full 32-edge chunks run a
// 4-way-unrolled gather (4 independent LDG.64 in flight) for MLP.
__global__ void k_agg(float* __restrict__ out) {
    __shared__ int    sns[8][32];
    __shared__ float4 al[8][32];
    int w = threadIdx.x >> 5;
    int lane = threadIdx.x & 31;
    int t = blockIdx.x * 8 + w;
    if (t >= N_NODES) return;

    int start = d_off[t];
    int end = d_off[t + 1];
    float4 st = d_stgt4[t];

    int hsel = lane >> 3;
    const __half* hwbase = d_Hwh + (long)lane * 4;
    float4 acc = make_float4(0.f, 0.f, 0.f, 0.f);
    float s0 = 0.f, s1 = 0.f, s2 = 0.f, s3 = 0.f;

    for (int base = start; base < end; base += 32) {
        int i = base + lane;
        float ax = 0.f, ay = 0.f, az = 0.f, aw = 0.f;
        int sn = 0;
        if (i < end) {
            sn = d_sorted_src[i];
            float4 e4 = d_ssrc4[sn];
            float e0 = e4.x + st.x; e0 = fmaxf(e0, 0.2f * e0);
            float e1 = e4.y + st.y; e1 = fmaxf(e1, 0.2f * e1);
            float e2 = e4.z + st.z; e2 = fmaxf(e2, 0.2f * e2);
            float e3 = e4.w + st.w; e3 = fmaxf(e3, 0.2f * e3);
            ax = __expf(e0);
            ay = __expf(e1);
            az = __expf(e2);
            aw = __expf(e3);
            s0 += ax; s1 += ay; s2 += az; s3 += aw;
        }
        sns[w][lane] = sn;
        al[w][lane] = make_float4(ax, ay, az, aw);
        __syncwarp();
        int cnt = end - base;
        if (cnt >= 32) {
#pragma unroll
            for (int j0 = 0; j0 < 32; j0 += 4) {
                int sj0 = sns[w][j0 + 0];
                int sj1 = sns[w][j0 + 1];
                int sj2 = sns[w][j0 + 2];
                int sj3 = sns[w][j0 + 3];
                uint2 h0 = *(const uint2*)(hwbase + (long)sj0 * CTOT);
                uint2 h1 = *(const uint2*)(hwbase + (long)sj1 * CTOT);
                uint2 h2 = *(const uint2*)(hwbase + (long)sj2 * CTOT);
                uint2 h3 = *(const uint2*)(hwbase + (long)sj3 * CTOT);
                float a0 = ((const float*)&al[w][j0 + 0])[hsel];
                float a1 = ((const float*)&al[w][j0 + 1])[hsel];
                float a2 = ((const float*)&al[w][j0 + 2])[hsel];
                float a3 = ((const float*)&al[w][j0 + 3])[hsel];
                float2 f;
                f = __half22float2(*(const __half2*)&h0.x);
                acc.x += a0 * f.x; acc.y += a0 * f.y;
                f = __half22float2(*(const __half2*)&h0.y);
                acc.z += a0 * f.x; acc.w += a0 * f.y;
                f = __half22float2(*(const __half2*)&h1.x);
                acc.x += a1 * f.x; acc.y += a1 * f.y;
                f = __half22float2(*(const __half2*)&h1.y);
                acc.z += a1 * f.x; acc.w += a1 * f.y;
                f = __half22float2(*(const __half2*)&h2.x);
                acc.x += a2 * f.x; acc.y += a2 * f.y;
                f = __half22float2(*(const __half2*)&h2.y);
                acc.z += a2 * f.x; acc.w += a2 * f.y;
                f = __half22float2(*(const __half2*)&h3.x);
                acc.x += a3 * f.x; acc.y += a3 * f.y;
                f = __half22float2(*(const __half2*)&h3.y);
                acc.z += a3 * f.x; acc.w += a3 * f.y;
            }
        } else {
            for (int j = 0; j < cnt; j++) {
                int sj = sns[w][j];
                float a = ((const float*)&al[w][j])[hsel];
                uint2 hv = *(const uint2*)(hwbase + (long)sj * CTOT);
                float2 f01 = __half22float2(*(const __half2*)&hv.x);
                float2 f23 = __half22float2(*(const __half2*)&hv.y);
                acc.x += a * f01.x;
                acc.y += a * f01.y;
                acc.z += a * f23.x;
                acc.w += a * f23.y;
            }
        }
        __syncwarp();
    }

#pragma unroll
    for (int off = 16; off > 0; off >>= 1) {
        s0 += __shfl_xor_sync(0xffffffffu, s0, off);
        s1 += __shfl_xor_sync(0xffffffffu, s1, off);
        s2 += __shfl_xor_sync(0xffffffffu, s2, off);
        s3 += __shfl_xor_sync(0xffffffffu, s3, off);
    }
    float sh = (hsel == 0) ? s0 : (hsel == 1) ? s1 : (hsel == 2) ? s2 : s3;
    float inv = (sh > 0.f) ? 1.f / sh : 0.f;
    acc.x *= inv; acc.y *= inv; acc.z *= inv; acc.w *= inv;

    float4 r;
    r.x = acc.x > 0.f ? acc.x : expm1f(acc.x);
    r.y = acc.y > 0.f ? acc.y : expm1f(acc.y);
    r.z = acc.z > 0.f ? acc.z : expm1f(acc.z);
    r.w = acc.w > 0.f ? acc.w : expm1f(acc.w);
    int o = (lane & 7) * 4;
    *(float4*)(out + ((long)hsel * N_NODES + t) * DOUT + o) = r;
}

// ---------------- launcher ----------------
// Two-stream fork inside the captured graph: the edge-sort chain (stream s2)
// runs concurrently with k_gemm (capture-origin stream); k_agg joins both.
// Issue order puts k_gemm at position 4 so the ncu -s5-c1 window (which has
// landed on issue #4 every round) profiles the GEMM next time.
extern "C" void kernel_launch(void* const* d_in, const int* in_sizes, int n_in,
                              void* d_out, int out_size) {
    const float* Hin  = (const float*)d_in[0];
    const int*   ei   = (const int*)d_in[1];
    const float* W    = (const float*)d_in[2];
    const float* Asrc = (const float*)d_in[3];
    const float* Atgt = (const float*)d_in[4];
    float* out = (float*)d_out;

    static cudaStream_t s2 = 0;
    static cudaEvent_t evFork = 0, evJoin = 0;
    static int inited = 0;
    if (!inited) {
        cudaStreamCreateWithFlags(&s2, cudaStreamNonBlocking);
        cudaEventCreateWithFlags(&evFork, cudaEventDisableTiming);
        cudaEventCreateWithFlags(&evJoin, cudaEventDisableTiming);
        cudaFuncSetAttribute(k_gemm,
                             cudaFuncAttributeMaxDynamicSharedMemorySize,
                             GEMM_SMEM);
        inited = 1;
    }

    // fork: s2 branches off the capture-origin (legacy) stream
    cudaEventRecord(evFork, 0);
    cudaStreamWaitEvent(s2, evFork, 0);

    // branch A (s2), part 1
    k_init<<<(N_NODES + 255) / 256, 256, 0, s2>>>((const unsigned int*)ei);   // #1
    k_hist<<<(N_EDGES + 255) / 256, 256, 0, s2>>>(ei);                        // #2
    k_scan1<<<NB_SCAN, 256, 0, s2>>>();                                       // #3

    // branch B (origin stream): feature transform + scores  -> issue #4
    k_gemm<<<(N_NODES + NPB - 1) / NPB, 256, GEMM_SMEM>>>(Hin, W, Asrc, Atgt);

    // branch A (s2), part 2
    k_scan3<<<NB_SCAN, 1024, 0, s2>>>();                                      // #5
    k_scatter<<<(N_EDGES + 255) / 256, 256, 0, s2>>>(ei);                     // #6
    cudaEventRecord(evJoin, s2);

    // join, then aggregate
    cudaStreamWaitEvent(0, evJoin, 0);
    k_agg<<<(N_NODES + 7) / 8, 256>>>(out);                                   // #7
}

// round 16
// speedup vs baseline: 1.4034x; 1.4034x over previous
#include <cuda_runtime.h>
#include <cuda_fp16.h>
#include <math.h>

#define N_NODES 100000
#define N_EDGES 1600000
#define NH 4
#define DIN 128
#define DOUT 32
#define NB_SCAN 98   // 98*1024 = 100352 >= N_NODES

#define CTOT 128              // NH*DOUT combined output cols
#define MPITCH 136            // smem pitch in halves (272B rows: LDSM conflict-free)
#define GEMM_SMEM (2 * 128 * MPITCH * 2)   // H tile + W tile, fp16: 69632 B

// ---------------- scratch (static __device__, no allocation) ----------------
__device__ __align__(16) __half d_Hwh[N_NODES * CTOT];  // [n][c] fp16, 25.6MB
__device__ __align__(16) __half d_Wh[CTOT * DIN];       // W as fp16 [c][k]
__device__ float  d_qs[NH * DIN];         // q_src[h][k] = sum_o Asrc[h][o] W[h][o][k]
__device__ float  d_qt[NH * DIN];
__device__ float4 d_ssrc4[N_NODES];       // [n] -> (s_src for h=0..3)
__device__ float4 d_stgt4[N_NODES];
__device__ int    d_hist[N_NODES];
__device__ int    d_off[N_NODES + 1];
__device__ int    d_cursor[N_NODES];
__device__ int    d_blocksums[128];
__device__ int    d_sorted_src[N_EDGES];
__device__ int    d_is64;

__device__ __forceinline__ unsigned smem_u32(const void* p) {
    unsigned a;
    asm("{ .reg .u64 t; cvta.to.shared.u64 t, %1; cvt.u32.u64 %0, t; }"
        : "=r"(a) : "l"(p));
    return a;
}

#define LDSM4(r, addr)                                                        \
    asm volatile("ldmatrix.sync.aligned.m8n8.x4.shared.b16 {%0,%1,%2,%3}, [%4];" \
        : "=r"((r)[0]), "=r"((r)[1]), "=r"((r)[2]), "=r"((r)[3]) : "r"(addr))

#define MMA16816(d, a, b)                                                     \
    asm volatile("mma.sync.aligned.m16n8k16.row.col.f32.f16.f16.f32 "         \
        "{%0,%1,%2,%3}, {%4,%5,%6,%7}, {%8,%9}, {%0,%1,%2,%3};"               \
        : "+f"((d)[0]), "+f"((d)[1]), "+f"((d)[2]), "+f"((d)[3])              \
        : "r"((a)[0]), "r"((a)[1]), "r"((a)[2]), "r"((a)[3]),                 \
          "r"((b)[0]), "r"((b)[1]))

// ---------------- init: zero hist + detect edge dtype ----------------
// int64 with values < 2^31 => every odd 32-bit word is zero.
__global__ void k_init(const unsigned int* __restrict__ w) {
    int i = blockIdx.x * 256 + threadIdx.x;
    if (i < N_NODES) d_hist[i] = 0;
    if (blockIdx.x == 0) {
        int nz = 0;
        for (int j = 0; j < 8; j++)
            nz |= (w[2 * (threadIdx.x * 8 + j) + 1] != 0u) ? 1 : 0;
        int any = __syncthreads_or(nz);
        if (threadIdx.x == 0) d_is64 = any ? 0 : 1;
    }
}

// histogram of targets, reading edge_index directly
__global__ void k_hist(const int* __restrict__ p) {
    int e = blockIdx.x * blockDim.x + threadIdx.x;
    if (e >= N_EDGES) return;
    int t = d_is64 ? p[2 * (N_EDGES + e)] : p[N_EDGES + e];
    atomicAdd(&d_hist[t], 1);
}

// ---------------- block sums of hist (shfl) ----------------
__global__ void k_scan1() {
    __shared__ int ws[8];
    int b = blockIdx.x, tid = threadIdx.x;
    int lane = tid & 31, wid = tid >> 5;
    int sum = 0;
    for (int j = 0; j < 4; j++) {
        int idx = b * 1024 + tid + j * 256;
        if (idx < N_NODES) sum += d_hist[idx];
    }
#pragma unroll
    for (int off = 16; off > 0; off >>= 1)
        sum += __shfl_xor_sync(0xffffffffu, sum, off);
    if (lane == 0) ws[wid] = sum;
    __syncthreads();
    if (tid == 0) {
        int s = 0;
        for (int j = 0; j < 8; j++) s += ws[j];
        d_blocksums[b] = s;
    }
}

// scan of hist: shfl-based, with inlined redundant scan of the 98 block sums
__global__ void k_scan3() {
    __shared__ int bs[128];
    __shared__ int warpsums[32];
    int b = blockIdx.x, tid = threadIdx.x;
    int lane = tid & 31, wid = tid >> 5;

    if (tid < 128) bs[tid] = (tid < NB_SCAN) ? d_blocksums[tid] : 0;
    __syncthreads();
    if (wid == 0) {
        int a0 = bs[4 * lane], a1 = bs[4 * lane + 1];
        int a2 = bs[4 * lane + 2], a3 = bs[4 * lane + 3];
        int s = a0 + a1 + a2 + a3;
        int inc = s;
#pragma unroll
        for (int off = 1; off < 32; off <<= 1) {
            int n = __shfl_up_sync(0xffffffffu, inc, off);
            if (lane >= off) inc += n;
        }
        int excl = inc - s;
        bs[4 * lane]     = excl;
        bs[4 * lane + 1] = excl + a0;
        bs[4 * lane + 2] = excl + a0 + a1;
        bs[4 * lane + 3] = excl + a0 + a1 + a2;
    }
    __syncthreads();
    int blockbase = bs[b];

    int idx = b * 1024 + tid;
    int v = (idx < N_NODES) ? d_hist[idx] : 0;
    int inc = v;
#pragma unroll
    for (int off = 1; off < 32; off <<= 1) {
        int n = __shfl_up_sync(0xffffffffu, inc, off);
        if (lane >= off) inc += n;
    }
    if (lane == 31) warpsums[wid] = inc;
    __syncthreads();
    if (wid == 0) {
        int wv = warpsums[lane];
        int winc = wv;
#pragma unroll
        for (int off = 1; off < 32; off <<= 1) {
            int n = __shfl_up_sync(0xffffffffu, winc, off);
            if (lane >= off) winc += n;
        }
        warpsums[lane] = winc - wv;
    }
    __syncthreads();
    if (idx < N_NODES) {
        int excl = inc - v + warpsums[wid] + blockbase;
        d_off[idx] = excl;
        d_cursor[idx] = excl;
    }
    if (b == 0 && tid == 0) d_off[N_NODES] = N_EDGES;
}

// scatter src ids into CSR order, reading edge_index directly
__global__ void k_scatter(const int* __restrict__ p) {
    int e = blockIdx.x * blockDim.x + threadIdx.x;
    if (e >= N_EDGES) return;
    int s, t;
    if (d_is64) {
        s = p[2 * e];
        t = p[2 * (N_EDGES + e)];
    } else {
        s = p[e];
        t = p[N_EDGES + e];
    }
    int pos = atomicAdd(&d_cursor[t], 1);
    d_sorted_src[pos] = s;
}

// ---------------- prep: q-vectors (fp32) + W -> fp16 ----------------
// q_s[h][k] = sum_o Asrc[h][o] * W[h][o][k]; exact-score path bypasses Hw.
__global__ void k_prep(const float* __restrict__ W,
                       const float* __restrict__ Asrc,
                       const float* __restrict__ Atgt) {
    int tid = threadIdx.x;   // 512 threads
    int h = tid >> 7, k = tid & 127;
    float qs = 0.f, qt = 0.f;
    for (int o = 0; o < DOUT; o++) {
        float wv = W[(h * DOUT + o) * DIN + k];
        qs += Asrc[h * DOUT + o] * wv;
        qt += Atgt[h * DOUT + o] * wv;
    }
    d_qs[h * DIN + k] = qs;
    d_qt[h * DIN + k] = qt;

    __half2* Wh2 = (__half2*)d_Wh;
    for (int idx = tid; idx < CTOT * DIN / 2; idx += 512)
        Wh2[idx] = __floats2half2_rn(W[2 * idx], W[2 * idx + 1]);
}

// ---------------- exact fp32 scores: s = H_in . q ----------------
// One warp per 8 nodes; lane = float4 column chunk; 8 butterfly reductions.
__global__ void k_score(const float* __restrict__ Hin) {
    int gw = blockIdx.x * 8 + (threadIdx.x >> 5);
    int lane = threadIdx.x & 31;
    if (gw >= N_NODES / 8) return;
    int n0 = gw * 8;

    float4 qs[4], qt[4];
#pragma unroll
    for (int h = 0; h < 4; h++) {
        qs[h] = ((const float4*)d_qs)[h * 32 + lane];
        qt[h] = ((const float4*)d_qt)[h * 32 + lane];
    }
    const float4* H4 = (const float4*)Hin;

    for (int i = 0; i < 8; i++) {
        int n = n0 + i;
        float4 hv = H4[n * 32 + lane];
        float v[8];
#pragma unroll
        for (int h = 0; h < 4; h++) {
            v[h]     = hv.x * qs[h].x + hv.y * qs[h].y + hv.z * qs[h].z + hv.w * qs[h].w;
            v[4 + h] = hv.x * qt[h].x + hv.y * qt[h].y + hv.z * qt[h].z + hv.w * qt[h].w;
        }
#pragma unroll
        for (int off = 16; off > 0; off >>= 1)
#pragma unroll
            for (int j = 0; j < 8; j++)
                v[j] += __shfl_xor_sync(0xffffffffu, v[j], off);
        if (lane == 0) {
            d_ssrc4[n] = make_float4(v[0], v[1], v[2], v[3]);
            d_stgt4[n] = make_float4(v[4], v[5], v[6], v[7]);
        }
    }
}

// ---------------- Hw via fp16 tensor cores (HMMA m16n8k16) ----------------
// Block: 128 nodes x 128 cols, 256 threads / 8 warps, warp tile 32x64.
// H tile converted f32->f16 into pitched smem; W fp16 tile from d_Wh.
__global__ void __launch_bounds__(256, 2) k_gemm_mma(const float* __restrict__ Hin) {
    extern __shared__ __half sm[];
    __half* Hsh = sm;                    // [128][MPITCH]
    __half* Wsh = sm + 128 * MPITCH;     // [128][MPITCH]

    int tid = threadIdx.x;
    int lane = tid & 31, wid = tid >> 5;
    int wm = wid & 3;    // m-group: rows wm*32..+31
    int wn = wid >> 2;   // n-group: cols wn*64..+63
    int n0 = blockIdx.x * 128;

    // Load W fp16 tile (32KB) from global
    const unsigned* Wg = (const unsigned*)d_Wh;
    for (int it = 0; it < 32; it++) {
        int idx = tid + it * 256;            // uint index (2 halves)
        int row = idx >> 6, c2 = idx & 63;
        *(unsigned*)((char*)Wsh + row * (MPITCH * 2) + c2 * 4) = Wg[idx];
    }

    // Load H tile f32 -> f16
    const float4* H4 = (const float4*)Hin;
    for (int it = 0; it < 16; it++) {
        int idx = tid + it * 256;            // float4 index
        int row = idx >> 5, c4 = idx & 31;
        int n = n0 + row;
        float4 v = make_float4(0.f, 0.f, 0.f, 0.f);
        if (n < N_NODES) v = H4[n * 32 + c4];
        __half2 lo = __floats2half2_rn(v.x, v.y);
        __half2 hi = __floats2half2_rn(v.z, v.w);
        uint2 pk = make_uint2(*(unsigned*)&lo, *(unsigned*)&hi);
        *(uint2*)((char*)Hsh + row * (MPITCH * 2) + c4 * 8) = pk;
    }
    __syncthreads();

    unsigned base = smem_u32(sm);
    unsigned Hb = base, Wb = base + 128 * MPITCH * 2;

    // ldmatrix lane address bases (bytes)
    unsigned aAddr0 = Hb + (unsigned)((wm * 32 + (lane & 15)) * (MPITCH * 2))
                         + ((lane & 16) ? 16u : 0u);
    unsigned bAddr0 = Wb + (unsigned)((wn * 64 + (lane & 7) + ((lane & 16) ? 8 : 0)) * (MPITCH * 2))
                         + ((lane & 8) ? 16u : 0u);

    float acc[2][8][4];
#pragma unroll
    for (int mt = 0; mt < 2; mt++)
#pragma unroll
        for (int nt = 0; nt < 8; nt++)
#pragma unroll
            for (int r = 0; r < 4; r++) acc[mt][nt][r] = 0.f;

#pragma unroll
    for (int ks = 0; ks < 8; ks++) {
        unsigned a[2][4];
#pragma unroll
        for (int mt = 0; mt < 2; mt++)
            LDSM4(a[mt], aAddr0 + ks * 32 + mt * 16 * (MPITCH * 2));
        unsigned b[8][2];
#pragma unroll
        for (int p = 0; p < 4; p++) {
            unsigned r4[4];
            LDSM4(r4, bAddr0 + ks * 32 + p * 16 * (MPITCH * 2));
            b[2 * p][0] = r4[0]; b[2 * p][1] = r4[1];
            b[2 * p + 1][0] = r4[2]; b[2 * p + 1][1] = r4[3];
        }
#pragma unroll
        for (int mt = 0; mt < 2; mt++)
#pragma unroll
            for (int nt = 0; nt < 8; nt++)
                MMA16816(acc[mt][nt], a[mt], b[nt]);
    }

    // Epilogue: fp16 Hw store (half2 per thread per tile-row)
    int g = lane >> 2, t4 = lane & 3;
#pragma unroll
    for (int mt = 0; mt < 2; mt++) {
#pragma unroll
        for (int nt = 0; nt < 8; nt++) {
            int r0 = n0 + wm * 32 + mt * 16 + g;
            int c = wn * 64 + nt * 8 + 2 * t4;
            if (r0 < N_NODES) {
                __half2 h01 = __floats2half2_rn(acc[mt][nt][0], acc[mt][nt][1]);
                *(__half2*)&d_Hwh[r0 * CTOT + c] = h01;
            }
            int r1 = r0 + 8;
            if (r1 < N_NODES) {
                __half2 h23 = __floats2half2_rn(acc[mt][nt][2], acc[mt][nt][3]);
                *(__half2*)&d_Hwh[r1 * CTOT + c] = h23;
            }
        }
    }
}

// ---------------- per-target softmax + aggregation + elu (all 4 heads) -------
// One warp per target node, single pass: unnormalized exp-weighted sums plus
// per-head denominators, normalize at the end (no max-subtraction needed).
__global__ void k_agg(float* __restrict__ out) {
    __shared__ int    sns[8][32];
    __shared__ float4 al[8][32];
    int w = threadIdx.x >> 5;
    int lane = threadIdx.x & 31;
    int t = blockIdx.x * 8 + w;
    if (t >= N_NODES) return;

    int start = d_off[t];
    int end = d_off[t + 1];
    float4 st = d_stgt4[t];

    int hsel = lane >> 3;
    const __half* hwbase = d_Hwh + (long)lane * 4;
    float4 acc = make_float4(0.f, 0.f, 0.f, 0.f);
    float s0 = 0.f, s1 = 0.f, s2 = 0.f, s3 = 0.f;

    for (int base = start; base < end; base += 32) {
        int i = base + lane;
        float ax = 0.f, ay = 0.f, az = 0.f, aw = 0.f;
        int sn = 0;
        if (i < end) {
            sn = d_sorted_src[i];
            float4 e4 = d_ssrc4[sn];
            float e0 = e4.x + st.x; e0 = fmaxf(e0, 0.2f * e0);
            float e1 = e4.y + st.y; e1 = fmaxf(e1, 0.2f * e1);
            float e2 = e4.z + st.z; e2 = fmaxf(e2, 0.2f * e2);
            float e3 = e4.w + st.w; e3 = fmaxf(e3, 0.2f * e3);
            ax = __expf(e0);
            ay = __expf(e1);
            az = __expf(e2);
            aw = __expf(e3);
            s0 += ax; s1 += ay; s2 += az; s3 += aw;
        }
        sns[w][lane] = sn;
        al[w][lane] = make_float4(ax, ay, az, aw);
        __syncwarp();
        int cnt = end - base;
        if (cnt > 32) cnt = 32;
        for (int j = 0; j < cnt; j++) {
            int sj = sns[w][j];
            float a = ((const float*)&al[w][j])[hsel];
            uint2 hv = *(const uint2*)(hwbase + (long)sj * CTOT);
            float2 f01 = __half22float2(*(const __half2*)&hv.x);
            float2 f23 = __half22float2(*(const __half2*)&hv.y);
            acc.x += a * f01.x;
            acc.y += a * f01.y;
            acc.z += a * f23.x;
            acc.w += a * f23.y;
        }
        __syncwarp();
    }

#pragma unroll
    for (int off = 16; off > 0; off >>= 1) {
        s0 += __shfl_xor_sync(0xffffffffu, s0, off);
        s1 += __shfl_xor_sync(0xffffffffu, s1, off);
        s2 += __shfl_xor_sync(0xffffffffu, s2, off);
        s3 += __shfl_xor_sync(0xffffffffu, s3, off);
    }
    float sh = (hsel == 0) ? s0 : (hsel == 1) ? s1 : (hsel == 2) ? s2 : s3;
    float inv = (sh > 0.f) ? 1.f / sh : 0.f;
    acc.x *= inv; acc.y *= inv; acc.z *= inv; acc.w *= inv;

    float4 r;
    r.x = acc.x > 0.f ? acc.x : expm1f(acc.x);
    r.y = acc.y > 0.f ? acc.y : expm1f(acc.y);
    r.z = acc.z > 0.f ? acc.z : expm1f(acc.z);
    r.w = acc.w > 0.f ? acc.w : expm1f(acc.w);
    int o = (lane & 7) * 4;
    *(float4*)(out + ((long)hsel * N_NODES + t) * DOUT + o) = r;
}

// ---------------- launcher ----------------
// Fork/join graph: sort chain on s2 overlaps prep/score/gemm on the origin
// stream; k_agg joins both. k_gemm_mma sits at issue #4 for the ncu window.
extern "C" void kernel_launch(void* const* d_in, const int* in_sizes, int n_in,
                              void* d_out, int out_size) {
    const float* Hin  = (const float*)d_in[0];
    const int*   ei   = (const int*)d_in[1];
    const float* W    = (const float*)d_in[2];
    const float* Asrc = (const float*)d_in[3];
    const float* Atgt = (const float*)d_in[4];
    float* out = (float*)d_out;

    static cudaStream_t s2 = 0;
    static cudaEvent_t evFork = 0, evJoin = 0;
    static int inited = 0;
    if (!inited) {
        cudaStreamCreateWithFlags(&s2, cudaStreamNonBlocking);
        cudaEventCreateWithFlags(&evFork, cudaEventDisableTiming);
        cudaEventCreateWithFlags(&evJoin, cudaEventDisableTiming);
        cudaFuncSetAttribute(k_gemm_mma,
                             cudaFuncAttributeMaxDynamicSharedMemorySize,
                             GEMM_SMEM);
        inited = 1;
    }

    // fork: s2 branches off the capture-origin (legacy) stream
    cudaEventRecord(evFork, 0);
    cudaStreamWaitEvent(s2, evFork, 0);

    k_init<<<(N_NODES + 255) / 256, 256, 0, s2>>>((const unsigned int*)ei);   // #1
    k_prep<<<1, 512>>>(W, Asrc, Atgt);                                        // #2
    k_score<<<(N_NODES / 8 + 7) / 8, 256>>>(Hin);                             // #3
    k_gemm_mma<<<(N_NODES + 127) / 128, 256, GEMM_SMEM>>>(Hin);               // #4

    k_hist<<<(N_EDGES + 255) / 256, 256, 0, s2>>>(ei);                        // #5
    k_scan1<<<NB_SCAN, 256, 0, s2>>>();                                       // #6
    k_scan3<<<NB_SCAN, 1024, 0, s2>>>();                                      // #7
    k_scatter<<<(N_EDGES + 255) / 256, 256, 0, s2>>>(ei);                     // #8
    cudaEventRecord(evJoin, s2);

    // join, then aggregate
    cudaStreamWaitEvent(0, evJoin, 0);
    k_agg<<<(N_NODES + 7) / 8, 256>>>(out);                                   // #9
}